// round 2
// baseline (speedup 1.0000x reference)
#include <cuda_runtime.h>
#include <cstdint>
#include <float.h>

#define NB 2048     // batch
#define NH 50       // history
#define ND 128      // dim
#define NV 100000   // vocab
#define NK 10       // top_k

#define BM 128
#define BN 128
#define AP 132      // smem row pitch in floats (132*4=528 bytes, 16B-aligned rows)

typedef unsigned long long ull;

__device__ float g_ctx[NB * ND];

// ---------------------------------------------------------------------------
// Kernel 1: ctx = mean(ctab[ids], axis=1) @ W + b        [NB, ND]
// ---------------------------------------------------------------------------
__global__ void ctx_kernel(const int* __restrict__ ids,
                           const float* __restrict__ ctab,
                           const float* __restrict__ W,
                           const float* __restrict__ bias) {
    int r = blockIdx.x;
    int d = threadIdx.x;
    __shared__ float pooled[ND];

    float s = 0.0f;
    #pragma unroll 5
    for (int h = 0; h < NH; ++h) {
        int id = ids[r * NH + h];
        s += ctab[(long)id * ND + d];
    }
    pooled[d] = s * (1.0f / (float)NH);
    __syncthreads();

    float acc = bias[d];
    #pragma unroll 8
    for (int i = 0; i < ND; ++i)
        acc = fmaf(pooled[i], W[i * ND + d], acc);
    g_ctx[r * ND + d] = acc;
}

// ---------------------------------------------------------------------------
// Kernel 2: logits = ctx @ labelT   (f32, packed f32x2 FMA)
// 128x128 tile per CTA, 256 threads, 8x8 micro-tile per thread.
// ---------------------------------------------------------------------------
__device__ __forceinline__ ull pack_dup(float a) {
    ull u;
    asm("mov.b64 %0, {%1, %1};" : "=l"(u) : "f"(a));
    return u;
}
__device__ __forceinline__ ull pack2(float x, float y) {
    ull u;
    asm("mov.b64 %0, {%1, %2};" : "=l"(u) : "f"(x), "f"(y));
    return u;
}
__device__ __forceinline__ void fma2(ull& d, ull a, ull b) {
    asm("fma.rn.f32x2 %0, %1, %2, %3;" : "=l"(d) : "l"(a), "l"(b), "l"(d));
}
__device__ __forceinline__ void unpack2(ull u, float& lo, float& hi) {
    asm("mov.b64 {%0, %1}, %2;" : "=f"(lo), "=f"(hi) : "l"(u));
}

extern __shared__ float smem_gemm[];

__global__ __launch_bounds__(256, 1)
void gemm_kernel(const float* __restrict__ label, float* __restrict__ out) {
    float* sA = smem_gemm;            // [k][m] transposed, pitch AP
    float* sB = smem_gemm + ND * AP;  // [k][n] transposed, pitch AP

    const int tid = threadIdx.x;
    const int r0 = blockIdx.y * BM;
    const int n0 = blockIdx.x * BN;

    // Load A tile (ctx rows r0..r0+127) transposed into sA[k][m]
    #pragma unroll
    for (int it = 0; it < 16; ++it) {
        int L  = it * 256 + tid;      // float4 index, 4096 total
        int m  = L >> 5;              // 32 float4 per row of 128 floats
        int k4 = (L & 31) * 4;
        float4 v = *(const float4*)(g_ctx + (r0 + m) * ND + k4);
        sA[(k4 + 0) * AP + m] = v.x;
        sA[(k4 + 1) * AP + m] = v.y;
        sA[(k4 + 2) * AP + m] = v.z;
        sA[(k4 + 3) * AP + m] = v.w;
    }
    // Load B tile (label rows n0..n0+127) transposed into sB[k][n]
    #pragma unroll
    for (int it = 0; it < 16; ++it) {
        int L  = it * 256 + tid;
        int n  = L >> 5;
        int k4 = (L & 31) * 4;
        int gn = n0 + n;
        float4 v = make_float4(0.f, 0.f, 0.f, 0.f);
        if (gn < NV) v = *(const float4*)(label + (long)gn * ND + k4);
        sB[(k4 + 0) * AP + n] = v.x;
        sB[(k4 + 1) * AP + n] = v.y;
        sB[(k4 + 2) * AP + n] = v.z;
        sB[(k4 + 3) * AP + n] = v.w;
    }
    __syncthreads();

    const int tr = tid >> 4;          // 0..15
    const int tc = tid & 15;          // 0..15
    const float* pa = sA + tr * 8;
    const float* pb = sB + tc * 8;

    ull acc[8][4];
    #pragma unroll
    for (int i = 0; i < 8; ++i)
        #pragma unroll
        for (int j = 0; j < 4; ++j) acc[i][j] = 0ull;

    #pragma unroll 8
    for (int k = 0; k < ND; ++k) {
        float4 a0 = *(const float4*)(pa + k * AP);
        float4 a1 = *(const float4*)(pa + k * AP + 4);
        float4 b01 = *(const float4*)(pb + k * AP);
        float4 b23 = *(const float4*)(pb + k * AP + 4);
        ull bb[4];
        bb[0] = pack2(b01.x, b01.y);
        bb[1] = pack2(b01.z, b01.w);
        bb[2] = pack2(b23.x, b23.y);
        bb[3] = pack2(b23.z, b23.w);
        ull aa[8];
        aa[0] = pack_dup(a0.x); aa[1] = pack_dup(a0.y);
        aa[2] = pack_dup(a0.z); aa[3] = pack_dup(a0.w);
        aa[4] = pack_dup(a1.x); aa[5] = pack_dup(a1.y);
        aa[6] = pack_dup(a1.z); aa[7] = pack_dup(a1.w);
        #pragma unroll
        for (int i = 0; i < 8; ++i) {
            fma2(acc[i][0], aa[i], bb[0]);
            fma2(acc[i][1], aa[i], bb[1]);
            fma2(acc[i][2], aa[i], bb[2]);
            fma2(acc[i][3], aa[i], bb[3]);
        }
    }

    // Writeback: column group is fully in-range or fully out (NV % 8 == 0)
    int gc = n0 + tc * 8;
    if (gc < NV) {
        #pragma unroll
        for (int i = 0; i < 8; ++i) {
            long m = r0 + tr * 8 + i;
            float4 o0, o1;
            unpack2(acc[i][0], o0.x, o0.y);
            unpack2(acc[i][1], o0.z, o0.w);
            unpack2(acc[i][2], o1.x, o1.y);
            unpack2(acc[i][3], o1.z, o1.w);
            float* dst = out + m * (long)NV + gc;
            *(float4*)(dst)     = o0;
            *(float4*)(dst + 4) = o1;
        }
    }
}

// ---------------------------------------------------------------------------
// Kernel 3: per-row top-10 (value desc, index asc on ties) over NV logits
// ---------------------------------------------------------------------------
__device__ __forceinline__ void tk_insert(float v, int id, float (&tv)[NK], int (&ti)[NK]) {
    if (v > tv[NK - 1]) {
        tv[NK - 1] = v; ti[NK - 1] = id;
        #pragma unroll
        for (int j = NK - 1; j > 0; --j) {
            if (tv[j] > tv[j - 1]) {
                float fv = tv[j]; tv[j] = tv[j - 1]; tv[j - 1] = fv;
                int ii = ti[j]; ti[j] = ti[j - 1]; ti[j - 1] = ii;
            }
        }
    }
}

__global__ __launch_bounds__(256)
void topk_kernel(const float* __restrict__ logits,
                 float* __restrict__ out_ids,
                 float* __restrict__ out_scores) {
    const int row = blockIdx.x;
    const int tid = threadIdx.x;
    const float4* p = (const float4*)(logits + (long)row * NV);

    float tv[NK]; int ti[NK];
    #pragma unroll
    for (int j = 0; j < NK; ++j) { tv[j] = -FLT_MAX; ti[j] = 0; }

    for (int i = tid; i < NV / 4; i += 256) {
        float4 v = p[i];
        int base = i * 4;
        tk_insert(v.x, base + 0, tv, ti);
        tk_insert(v.y, base + 1, tv, ti);
        tk_insert(v.z, base + 2, tv, ti);
        tk_insert(v.w, base + 3, tv, ti);
    }

    __shared__ float sv[256 * NK];
    __shared__ int   si[256 * NK];
    #pragma unroll
    for (int j = 0; j < NK; ++j) { sv[tid * NK + j] = tv[j]; si[tid * NK + j] = ti[j]; }
    __syncthreads();

    for (int s = 128; s > 0; s >>= 1) {
        if (tid < s) {
            const float* Av = sv + tid * NK;
            const int*   Ai = si + tid * NK;
            const float* Bv = sv + (tid + s) * NK;
            const int*   Bi = si + (tid + s) * NK;
            float mv[NK]; int mi[NK];
            int pa = 0, pb = 0;
            #pragma unroll
            for (int t = 0; t < NK; ++t) {
                float av = Av[pa], bv = Bv[pb];
                int   ai = Ai[pa], bi = Bi[pb];
                bool takeA = (av > bv) || (av == bv && ai < bi);
                if (takeA) { mv[t] = av; mi[t] = ai; ++pa; }
                else       { mv[t] = bv; mi[t] = bi; ++pb; }
            }
            #pragma unroll
            for (int t = 0; t < NK; ++t) { sv[tid * NK + t] = mv[t]; si[tid * NK + t] = mi[t]; }
        }
        __syncthreads();
    }

    if (tid < NK) {
        out_ids[row * NK + tid]    = (float)si[tid];
        out_scores[row * NK + tid] = sv[tid];
    }
}

// ---------------------------------------------------------------------------
// Launch: inputs in metadata order:
//   0 context_ids [2048*50] i32, 1 context_embed_table [100000*128] f32,
//   2 label_embed_table [100000*128] f32, 3 proj_w [128*128] f32,
//   4 proj_b [128] f32, 5 top_k (unused, fixed 10)
// Output (f32): logits [2048*100000] ++ top_ids-as-float [2048*10] ++ top_scores [2048*10]
// ---------------------------------------------------------------------------
extern "C" void kernel_launch(void* const* d_in, const int* in_sizes, int n_in,
                              void* d_out, int out_size) {
    const int*   ids  = (const int*)d_in[0];
    const float* ctab = (const float*)d_in[1];
    const float* ltab = (const float*)d_in[2];
    const float* W    = (const float*)d_in[3];
    const float* bias = (const float*)d_in[4];

    float* out        = (float*)d_out;
    float* logits     = out;
    float* out_ids    = out + (long)NB * NV;
    float* out_scores = out_ids + NB * NK;

    ctx_kernel<<<NB, ND>>>(ids, ctab, W, bias);

    size_t smem = (size_t)2 * ND * AP * sizeof(float);  // 135168 B
    cudaFuncSetAttribute(gemm_kernel, cudaFuncAttributeMaxDynamicSharedMemorySize, (int)smem);
    dim3 grid((NV + BN - 1) / BN, NB / BM);
    gemm_kernel<<<grid, 256, smem>>>(ltab, logits);

    topk_kernel<<<NB, 256>>>(logits, out_ids, out_scores);
}

// round 4
// speedup vs baseline: 1.5468x; 1.5468x over previous
#include <cuda_runtime.h>
#include <cstdint>
#include <float.h>

#define NB 2048     // batch
#define NH 50       // history
#define ND 128      // dim (K)
#define NV 100000   // vocab
#define NK 10       // top_k

#define TM 128      // rowtile (batch)
#define TN 64       // coltile (vocab)
#define NCOLT ((NV + TN - 1) / TN)   // 1563 (last tile has 32 valid cols)
#define NCG 9                        // column groups
#define NRT (NB / TM)                // 16

#define APITCH 132                   // smem pitch in words (conflict-free frag loads)

// smem word offsets
#define OFF_AHI 0
#define OFF_ALO (TM * APITCH)                       // 16896
#define OFF_BHI (2 * TM * APITCH)                   // 33792
#define OFF_BLO (2 * TM * APITCH + TN * APITCH)     // 42240
#define SMEM_WORDS (2 * TM * APITCH + 2 * TN * APITCH)  // 50688 -> 202752 B

__device__ float g_ahi[NB * ND];
__device__ float g_alo[NB * ND];

__device__ __forceinline__ float tf32_rna(float x) {
    uint32_t u;
    asm("cvt.rna.tf32.f32 %0, %1;" : "=r"(u) : "f"(x));
    return __uint_as_float(u);
}

// m16n8k8 tf32 mma, f32 accumulate (sm_80+ base-target instruction)
__device__ __forceinline__ void mma8(float (&d)[4], const uint32_t (&a)[4], const uint32_t (&b)[2]) {
    asm("mma.sync.aligned.m16n8k8.row.col.f32.tf32.tf32.f32 "
        "{%0,%1,%2,%3}, {%4,%5,%6,%7}, {%8,%9}, {%0,%1,%2,%3};"
        : "+f"(d[0]), "+f"(d[1]), "+f"(d[2]), "+f"(d[3])
        : "r"(a[0]), "r"(a[1]), "r"(a[2]), "r"(a[3]), "r"(b[0]), "r"(b[1]));
}

// ---------------------------------------------------------------------------
// Kernel 1: ctx = mean(ctab[ids]) @ W + b, then tf32 hi/lo split
// ---------------------------------------------------------------------------
__global__ void ctx_kernel(const int* __restrict__ ids,
                           const float* __restrict__ ctab,
                           const float* __restrict__ W,
                           const float* __restrict__ bias) {
    int r = blockIdx.x;
    int d = threadIdx.x;
    __shared__ float pooled[ND];

    float s = 0.0f;
    #pragma unroll 5
    for (int h = 0; h < NH; ++h) {
        int id = ids[r * NH + h];
        s += ctab[(long)id * ND + d];
    }
    pooled[d] = s * (1.0f / (float)NH);
    __syncthreads();

    float acc = bias[d];
    #pragma unroll 8
    for (int i = 0; i < ND; ++i)
        acc = fmaf(pooled[i], W[i * ND + d], acc);

    float hi = tf32_rna(acc);
    float lo = tf32_rna(acc - hi);
    g_ahi[r * ND + d] = hi;
    g_alo[r * ND + d] = lo;
}

// ---------------------------------------------------------------------------
// Kernel 2: logits = ctx @ labelT via mma.sync 3xTF32
// Persistent CTA per (rowtile, colgroup). A hi/lo resident in smem,
// B tiles streamed with register prefetch.
// ---------------------------------------------------------------------------
extern __shared__ uint32_t sm_g[];

__global__ __launch_bounds__(256, 1)
void gemm_kernel(const float* __restrict__ label, float* __restrict__ out) {
    uint32_t* sAhi = sm_g + OFF_AHI;
    uint32_t* sAlo = sm_g + OFF_ALO;
    uint32_t* sBhi = sm_g + OFF_BHI;
    uint32_t* sBlo = sm_g + OFF_BLO;

    const int tid  = threadIdx.x;
    const int lane = tid & 31;
    const int wid  = tid >> 5;
    const int r0   = blockIdx.y * TM;

    // ---- Load resident A rowtile (pre-split hi/lo) ----
    {
        int m  = tid >> 1;
        int d0 = (tid & 1) * 64;
        const float4* ph = (const float4*)(g_ahi + (long)(r0 + m) * ND + d0);
        const float4* pl = (const float4*)(g_alo + (long)(r0 + m) * ND + d0);
        float* dh = (float*)(sAhi + m * APITCH + d0);
        float* dl = (float*)(sAlo + m * APITCH + d0);
        #pragma unroll
        for (int j = 0; j < 16; ++j) {
            *(float4*)(dh + j * 4) = ph[j];
            *(float4*)(dl + j * 4) = pl[j];
        }
    }

    // fragment bases
    const int aRow = (wid >> 1) * 32 + (lane >> 2);   // warp m-origin + groupID
    const int bCol = (wid & 1) * 32 + (lane >> 2);    // warp n-origin + groupID
    const int kq   = lane & 3;

    // B tile prefetch regs: thread covers vocab-row n=tid>>2, dims (tid&3)*4 + 16j
    const int pn = tid >> 2;
    const int pd = (tid & 3) * 4;
    float4 pf[8];

    int ct = blockIdx.x;
    // prefetch first tile
    {
        int gn = ct * TN + pn;
        if (gn < NV) {
            const float4* src = (const float4*)(label + (long)gn * ND + pd);
            #pragma unroll
            for (int j = 0; j < 8; ++j) pf[j] = src[j * 4];
        } else {
            #pragma unroll
            for (int j = 0; j < 8; ++j) pf[j] = make_float4(0.f, 0.f, 0.f, 0.f);
        }
    }

    while (true) {
        // ---- store prefetched B tile (tf32 hi/lo split) ----
        __syncthreads();
        {
            float* bh = (float*)(sBhi + pn * APITCH + pd);
            float* bl = (float*)(sBlo + pn * APITCH + pd);
            #pragma unroll
            for (int j = 0; j < 8; ++j) {
                float4 v = pf[j];
                float4 h, l;
                h.x = tf32_rna(v.x); l.x = tf32_rna(v.x - h.x);
                h.y = tf32_rna(v.y); l.y = tf32_rna(v.y - h.y);
                h.z = tf32_rna(v.z); l.z = tf32_rna(v.z - h.z);
                h.w = tf32_rna(v.w); l.w = tf32_rna(v.w - h.w);
                *(float4*)(bh + j * 16) = h;
                *(float4*)(bl + j * 16) = l;
            }
        }
        __syncthreads();

        // ---- prefetch next tile into regs (hidden under compute) ----
        const int nct = ct + NCG;
        if (nct < NCOLT) {
            int gn = nct * TN + pn;
            if (gn < NV) {
                const float4* src = (const float4*)(label + (long)gn * ND + pd);
                #pragma unroll
                for (int j = 0; j < 8; ++j) pf[j] = src[j * 4];
            } else {
                #pragma unroll
                for (int j = 0; j < 8; ++j) pf[j] = make_float4(0.f, 0.f, 0.f, 0.f);
            }
        }

        // ---- compute 128x64 tile: warp 32x32, 3 tf32 passes fused per k-step ----
        float acc[2][4][4];
        #pragma unroll
        for (int mi = 0; mi < 2; ++mi)
            #pragma unroll
            for (int ni = 0; ni < 4; ++ni)
                #pragma unroll
                for (int q = 0; q < 4; ++q) acc[mi][ni][q] = 0.0f;

        #pragma unroll 4
        for (int k0 = 0; k0 < ND; k0 += 8) {
            uint32_t ah[2][4], al[2][4], bh[4][2], bl[4][2];
            #pragma unroll
            for (int mi = 0; mi < 2; ++mi) {
                int base = (aRow + mi * 16) * APITCH + k0 + kq;
                ah[mi][0] = sAhi[base];
                ah[mi][1] = sAhi[base + 8 * APITCH];
                ah[mi][2] = sAhi[base + 4];
                ah[mi][3] = sAhi[base + 8 * APITCH + 4];
                al[mi][0] = sAlo[base];
                al[mi][1] = sAlo[base + 8 * APITCH];
                al[mi][2] = sAlo[base + 4];
                al[mi][3] = sAlo[base + 8 * APITCH + 4];
            }
            #pragma unroll
            for (int ni = 0; ni < 4; ++ni) {
                int base = (bCol + ni * 8) * APITCH + k0 + kq;
                bh[ni][0] = sBhi[base];
                bh[ni][1] = sBhi[base + 4];
                bl[ni][0] = sBlo[base];
                bl[ni][1] = sBlo[base + 4];
            }
            #pragma unroll
            for (int mi = 0; mi < 2; ++mi)
                #pragma unroll
                for (int ni = 0; ni < 4; ++ni) {
                    mma8(acc[mi][ni], ah[mi], bh[ni]);   // hi*hi
                    mma8(acc[mi][ni], ah[mi], bl[ni]);   // hi*lo
                    mma8(acc[mi][ni], al[mi], bh[ni]);   // lo*hi
                }
        }

        // ---- epilogue: write tile to logits ----
        {
            const int n0 = ct * TN;
            #pragma unroll
            for (int mi = 0; mi < 2; ++mi) {
                long rg = r0 + (wid >> 1) * 32 + mi * 16 + (lane >> 2);
                float* o0 = out + rg * (long)NV;
                float* o1 = o0 + 8l * NV;
                #pragma unroll
                for (int ni = 0; ni < 4; ++ni) {
                    int cg = n0 + (wid & 1) * 32 + ni * 8 + 2 * (lane & 3);
                    if (cg < NV) {
                        *(float2*)(o0 + cg) = make_float2(acc[mi][ni][0], acc[mi][ni][1]);
                        *(float2*)(o1 + cg) = make_float2(acc[mi][ni][2], acc[mi][ni][3]);
                    }
                }
            }
        }

        if (nct >= NCOLT) break;
        ct = nct;
    }
}

// ---------------------------------------------------------------------------
// Kernel 3: per-row top-10 (value desc, index asc ties); vector-max prefilter
// ---------------------------------------------------------------------------
#define TKT 512

__device__ __forceinline__ void tk_insert(float v, int id, float (&tv)[NK], int (&ti)[NK]) {
    if (v > tv[NK - 1]) {
        tv[NK - 1] = v; ti[NK - 1] = id;
        #pragma unroll
        for (int j = NK - 1; j > 0; --j) {
            if (tv[j] > tv[j - 1]) {
                float fv = tv[j]; tv[j] = tv[j - 1]; tv[j - 1] = fv;
                int ii = ti[j]; ti[j] = ti[j - 1]; ti[j - 1] = ii;
            }
        }
    }
}

__global__ __launch_bounds__(TKT)
void topk_kernel(const float* __restrict__ logits,
                 float* __restrict__ out_ids,
                 float* __restrict__ out_scores) {
    const int row = blockIdx.x;
    const int tid = threadIdx.x;
    const float4* p = (const float4*)(logits + (long)row * NV);

    float tv[NK]; int ti[NK];
    #pragma unroll
    for (int j = 0; j < NK; ++j) { tv[j] = -FLT_MAX; ti[j] = 0; }

    for (int i = tid; i < NV / 4; i += TKT) {
        float4 v = p[i];
        float m = fmaxf(fmaxf(v.x, v.y), fmaxf(v.z, v.w));
        if (m > tv[NK - 1]) {
            int base = i * 4;
            tk_insert(v.x, base + 0, tv, ti);
            tk_insert(v.y, base + 1, tv, ti);
            tk_insert(v.z, base + 2, tv, ti);
            tk_insert(v.w, base + 3, tv, ti);
        }
    }

    __shared__ float sv[TKT * NK];
    __shared__ int   si[TKT * NK];
    #pragma unroll
    for (int j = 0; j < NK; ++j) { sv[tid * NK + j] = tv[j]; si[tid * NK + j] = ti[j]; }
    __syncthreads();

    for (int s = TKT / 2; s > 0; s >>= 1) {
        if (tid < s) {
            const float* Av = sv + tid * NK;
            const int*   Ai = si + tid * NK;
            const float* Bv = sv + (tid + s) * NK;
            const int*   Bi = si + (tid + s) * NK;
            float mv[NK]; int mi[NK];
            int pa = 0, pb = 0;
            #pragma unroll
            for (int t = 0; t < NK; ++t) {
                float av = Av[pa], bv = Bv[pb];
                int   ai = Ai[pa], bi = Bi[pb];
                bool takeA = (av > bv) || (av == bv && ai < bi);
                if (takeA) { mv[t] = av; mi[t] = ai; ++pa; }
                else       { mv[t] = bv; mi[t] = bi; ++pb; }
            }
            #pragma unroll
            for (int t = 0; t < NK; ++t) { sv[tid * NK + t] = mv[t]; si[tid * NK + t] = mi[t]; }
        }
        __syncthreads();
    }

    if (tid < NK) {
        out_ids[row * NK + tid]    = (float)si[tid];
        out_scores[row * NK + tid] = sv[tid];
    }
}

// ---------------------------------------------------------------------------
// Launch
// ---------------------------------------------------------------------------
extern "C" void kernel_launch(void* const* d_in, const int* in_sizes, int n_in,
                              void* d_out, int out_size) {
    const int*   ids  = (const int*)d_in[0];
    const float* ctab = (const float*)d_in[1];
    const float* ltab = (const float*)d_in[2];
    const float* W    = (const float*)d_in[3];
    const float* bias = (const float*)d_in[4];

    float* out        = (float*)d_out;
    float* logits     = out;
    float* out_ids    = out + (long)NB * NV;
    float* out_scores = out_ids + NB * NK;

    ctx_kernel<<<NB, ND>>>(ids, ctab, W, bias);

    size_t smem = (size_t)SMEM_WORDS * 4;   // 202752 bytes
    cudaFuncSetAttribute(gemm_kernel, cudaFuncAttributeMaxDynamicSharedMemorySize, (int)smem);
    dim3 grid(NCG, NRT);
    gemm_kernel<<<grid, 256, smem>>>(ltab, logits);

    topk_kernel<<<NB, TKT>>>(logits, out_ids, out_scores);
}